// round 6
// baseline (speedup 1.0000x reference)
#include <cuda_runtime.h>
#include <float.h>
#include <math.h>
#include <stdint.h>

#define BB 2
#define CC 256
#define NN 64
#define NCLS 10

// Scratch: templates [level][b][c][n] (n contiguous for vector loads in cor).
__device__ float g_tmpl[3 * BB * CC * NN];

// idx/labels may arrive as int64 (stride 2 int32 words, odd words 0) or int32.
__device__ __forceinline__ int lab_stride(const int* __restrict__ lab) {
    return ((lab[1] | lab[3] | lab[5]) == 0) ? 2 : 1;
}

// ---------------------------------------------------------------------------
// Kernel 1: templates. Block per (level,b,n), 256 threads. tx = tid&7 covers
// window x (contiguous loads); ty = tid>>3 covers channels (8 per thread);
// shfl-reduce over tx bits. (Validated: R2/R3 produced bit-identical output.)
// ---------------------------------------------------------------------------
__global__ void __launch_bounds__(256) tmpl_kernel(
    const float* __restrict__ x0, const float* __restrict__ x1,
    const float* __restrict__ x2, const float* __restrict__ centers,
    const int* __restrict__ idxp, const int* __restrict__ labp)
{
    const int bid   = blockIdx.x;             // [0, 3*B*N)
    const int level = bid / (BB * NN);
    const int r     = bid % (BB * NN);
    const int b     = r / NN;
    const int n     = r % NN;

    const int W = 64 >> level;
    const int s = 8 << level;

    const int tid = threadIdx.x;
    const int tx  = tid & 7;                  // window x lane
    const int ty  = tid >> 3;                 // channel base (0..31)

    const float cx = centers[(b * NN + n) * 2 + 0];
    const float cy = centers[(b * NN + n) * 2 + 1];
    const int istr = lab_stride(labp);
    const int idxv = idxp[(b * NN + n) * istr];

    const int ux = (int)floorf((cx - 0.5f) / (float)s + 0.5f);
    const int uy = (int)floorf((cy - 0.5f) / (float)s + 0.5f);
    const int xlo = max(0, ux - 3), xhi = min(W - 1, ux + 3);
    const int ylo = max(0, uy - 3), yhi = min(W - 1, uy + 3);

    const float alpha = -1.0f / 18.0f;        // -0.5/sigma^2, sigma=3

    int xi = xlo + tx;
    float wx = 0.f;
    if (xi <= xhi) { float d = (float)(xi * s) + 0.5f - cx; wx = expf(alpha * d * d); }
    xi = min(xi, W - 1);                      // in-bounds (weight already 0)

    float wy[7]; float Sy = 0.f;
    #pragma unroll
    for (int j = 0; j < 7; j++) {
        int yj = ylo + j;
        float w = 0.f;
        if (yj <= yhi) { float d = (float)(yj * s) + 0.5f - cy; w = expf(alpha * d * d); }
        wy[j] = w; Sy += w;
    }

    float Sx = wx;
    Sx += __shfl_xor_sync(0xffffffffu, Sx, 1);
    Sx += __shfl_xor_sync(0xffffffffu, Sx, 2);
    Sx += __shfl_xor_sync(0xffffffffu, Sx, 4);
    const float inv = (idxv == -1) ? 0.f : 1.f / (Sx * Sy + 1e-8f);

    const float* feat = (level == 0) ? x0 : (level == 1) ? x1 : x2;
    const float* fb = feat + (size_t)b * CC * W * W;

    #pragma unroll
    for (int k = 0; k < 8; k++) {
        const int c = ty + 32 * k;
        const float* fc = fb + (size_t)c * W * W + xi;
        float a = 0.f;
        #pragma unroll
        for (int j = 0; j < 7; j++) {
            int yj = min(ylo + j, W - 1);
            a += wy[j] * __ldg(fc + yj * W);
        }
        a *= wx;
        a += __shfl_xor_sync(0xffffffffu, a, 1);
        a += __shfl_xor_sync(0xffffffffu, a, 2);
        a += __shfl_xor_sync(0xffffffffu, a, 4);
        if (tx == 0)
            g_tmpl[((size_t)(level * BB + b) * CC + c) * NN + n] = a * inv;
    }
}

// ---------------------------------------------------------------------------
// Kernel 2: correlation + class-max + concat. 672 blocks x 256 thr (8 warps),
// block = (level, b, 16-pixel tile). Warp: px8 = lane&7, cg = lane>>3
// (4 x 64-channel groups); up = warp&3 splits users 4 ways (16 users/thread,
// acc[j] = users (2j, 2j+1) -- MUST match the epilogue's acc[u>>1] mapping);
// pb = warp>>2 picks pixel octet. Templates via __ldg (L1/L2 resident).
// ---------------------------------------------------------------------------
__global__ void __launch_bounds__(256, 4) cor_kernel(
    const float* __restrict__ x0, const float* __restrict__ x1,
    const float* __restrict__ x2, const int* __restrict__ labp,
    float* __restrict__ out)
{
    __shared__ int   slab[NN];
    __shared__ float pcmax[4][NCLS][16];

    const int bid = blockIdx.x;               // [0, 672)
    int level, b, tile;
    if (bid < 512)      { level = 0; b = bid >> 8;              tile = bid & 255; }
    else if (bid < 640) { level = 1; int q = bid - 512; b = q >> 6; tile = q & 63; }
    else                { level = 2; int q = bid - 640; b = q >> 4; tile = q & 15; }

    const int W  = 64 >> level;
    const int HW = W * W;
    const float* feat = (level == 0) ? x0 : (level == 1) ? x1 : x2;
    const size_t outOff = (level == 0) ? 0
                        : (level == 1) ? (size_t)(BB * 266 * 4096)
                        : (size_t)(BB * 266 * (4096 + 1024));

    if (threadIdx.x < NN) {
        int lstr = lab_stride(labp);
        slab[threadIdx.x] = labp[(b * NN + threadIdx.x) * lstr];
    }
    __syncthreads();

    const int lane = threadIdx.x & 31;
    const int warp = threadIdx.x >> 5;
    const int px8  = lane & 7;
    const int cg   = lane >> 3;               // channel group 0..3
    const int up   = warp & 3;                // user quarter 0..3
    const int pb   = warp >> 2;               // pixel octet 0..1
    const int p    = tile * 16 + pb * 8 + px8;

    const float* fp = feat + ((size_t)(b * CC + cg * 64)) * HW + p;
    float*       op = out + outOff + ((size_t)(b * 266 + cg * 64)) * HW + p;

    // templates for this (level,b): ulonglong2 = 4 users; 16 users = 4 loads
    const ulonglong2* T = (const ulonglong2*)(g_tmpl
                          + (size_t)(level * BB + b) * CC * NN);
    const int tIdx0 = (cg * 64) * (NN / 4) + up * 4;   // + c*16 per channel

    unsigned long long acc[8];                // acc[j] = users (2j, 2j+1)
    #pragma unroll
    for (int i = 0; i < 8; i++) acc[i] = 0ULL;

    #pragma unroll 4
    for (int c = 0; c < 64; c++) {
        const float f = __ldg(fp + (size_t)c * HW);
        if (up == 0) op[(size_t)c * HW] = f;  // feat passthrough (warp-uniform)
        unsigned long long f2;
        {
            uint32_t fb_ = __float_as_uint(f);
            asm("mov.b64 %0, {%1, %1};" : "=l"(f2) : "r"(fb_));
        }
        const ulonglong2* tc = T + tIdx0 + c * (NN / 4);
        #pragma unroll
        for (int q = 0; q < 4; q++) {
            ulonglong2 t = __ldg(tc + q);     // LDG.128: users 4q..4q+3
            asm("fma.rn.f32x2 %0, %1, %2, %0;" : "+l"(acc[2 * q])     : "l"(t.x), "l"(f2));
            asm("fma.rn.f32x2 %0, %1, %2, %0;" : "+l"(acc[2 * q + 1]) : "l"(t.y), "l"(f2));
        }
    }

    // sum the 4 channel groups (packed adds over lane bits 3,4)
    #pragma unroll
    for (int i = 0; i < 8; i++) {
        unsigned long long o = __shfl_xor_sync(0xffffffffu, acc[i], 8);
        asm("add.rn.f32x2 %0, %0, %1;" : "+l"(acc[i]) : "l"(o));
        o = __shfl_xor_sync(0xffffffffu, acc[i], 16);
        asm("add.rn.f32x2 %0, %0, %1;" : "+l"(acc[i]) : "l"(o));
    }

    // lanes cg==0 hold full 256-channel sums for this warp's 16 users
    if (cg == 0) {
        #pragma unroll
        for (int k = 0; k < NCLS; k++) {
            float m = -FLT_MAX;
            #pragma unroll
            for (int u = 0; u < 16; u++) {
                float v = (u & 1) ? __uint_as_float((uint32_t)(acc[u >> 1] >> 32))
                                  : __uint_as_float((uint32_t)(acc[u >> 1] & 0xffffffffu));
                if (slab[up * 16 + u] == k + 1) m = fmaxf(m, v);
            }
            pcmax[up][k][pb * 8 + px8] = m;
        }
    }
    __syncthreads();

    // combine 4 user quarters, apply any_cls -> 0, write class channels
    for (int t = threadIdx.x; t < NCLS * 16; t += 256) {
        const int k   = t >> 4;
        const int pix = t & 15;
        float v = fmaxf(fmaxf(pcmax[0][k][pix], pcmax[1][k][pix]),
                        fmaxf(pcmax[2][k][pix], pcmax[3][k][pix]));
        if (v == -FLT_MAX) v = 0.f;
        out[outOff + ((size_t)(b * 266 + 256 + k)) * HW + tile * 16 + pix] = v;
    }
}

// ---------------------------------------------------------------------------
extern "C" void kernel_launch(void* const* d_in, const int* in_sizes, int n_in,
                              void* d_out, int out_size)
{
    const float* x0      = (const float*)d_in[0];
    const float* x1      = (const float*)d_in[1];
    const float* x2      = (const float*)d_in[2];
    const float* centers = (const float*)d_in[3];
    const int*   idxp    = (const int*)d_in[4];
    const int*   labp    = (const int*)d_in[5];
    float* out = (float*)d_out;

    tmpl_kernel<<<3 * BB * NN, 256>>>(x0, x1, x2, centers, idxp, labp);
    cor_kernel<<<672, 256>>>(x0, x1, x2, labp, out);
}

// round 7
// speedup vs baseline: 1.5493x; 1.5493x over previous
#include <cuda_runtime.h>
#include <float.h>
#include <math.h>
#include <stdint.h>

#define BB 2
#define CC 256
#define NN 64
#define NCLS 10

// padded per-cgroup template region: 64ch*64u + 4 pad words (16B-aligned;
// 4100 mod 32 = 4 -> cgroups start on banks {0,4,8,12}: conflict-free)
#define CGPAD 4100

// Scratch: templates [level][b][c][n] (n contiguous for vector loads in cor).
__device__ float g_tmpl[3 * BB * CC * NN];

// idx/labels may arrive as int64 (stride 2 int32 words, odd words 0) or int32.
__device__ __forceinline__ int lab_stride(const int* __restrict__ lab) {
    return ((lab[1] | lab[3] | lab[5]) == 0) ? 2 : 1;
}

// ---------------------------------------------------------------------------
// Kernel 1: templates (R6 version — validated in a passing run).
// ---------------------------------------------------------------------------
__global__ void __launch_bounds__(256) tmpl_kernel(
    const float* __restrict__ x0, const float* __restrict__ x1,
    const float* __restrict__ x2, const float* __restrict__ centers,
    const int* __restrict__ idxp, const int* __restrict__ labp)
{
    const int bid   = blockIdx.x;             // [0, 3*B*N)
    const int level = bid / (BB * NN);
    const int r     = bid % (BB * NN);
    const int b     = r / NN;
    const int n     = r % NN;

    const int W = 64 >> level;
    const int s = 8 << level;

    const int tid = threadIdx.x;
    const int tx  = tid & 7;                  // window x lane
    const int ty  = tid >> 3;                 // channel base (0..31)

    const float cx = centers[(b * NN + n) * 2 + 0];
    const float cy = centers[(b * NN + n) * 2 + 1];
    const int istr = lab_stride(labp);
    const int idxv = idxp[(b * NN + n) * istr];

    const int ux = (int)floorf((cx - 0.5f) / (float)s + 0.5f);
    const int uy = (int)floorf((cy - 0.5f) / (float)s + 0.5f);
    const int xlo = max(0, ux - 3), xhi = min(W - 1, ux + 3);
    const int ylo = max(0, uy - 3), yhi = min(W - 1, uy + 3);

    const float alpha = -1.0f / 18.0f;        // -0.5/sigma^2, sigma=3

    int xi = xlo + tx;
    float wx = 0.f;
    if (xi <= xhi) { float d = (float)(xi * s) + 0.5f - cx; wx = expf(alpha * d * d); }
    xi = min(xi, W - 1);                      // in-bounds (weight already 0)

    float wy[7]; float Sy = 0.f;
    #pragma unroll
    for (int j = 0; j < 7; j++) {
        int yj = ylo + j;
        float w = 0.f;
        if (yj <= yhi) { float d = (float)(yj * s) + 0.5f - cy; w = expf(alpha * d * d); }
        wy[j] = w; Sy += w;
    }

    float Sx = wx;
    Sx += __shfl_xor_sync(0xffffffffu, Sx, 1);
    Sx += __shfl_xor_sync(0xffffffffu, Sx, 2);
    Sx += __shfl_xor_sync(0xffffffffu, Sx, 4);
    const float inv = (idxv == -1) ? 0.f : 1.f / (Sx * Sy + 1e-8f);

    const float* feat = (level == 0) ? x0 : (level == 1) ? x1 : x2;
    const float* fb = feat + (size_t)b * CC * W * W;

    #pragma unroll
    for (int k = 0; k < 8; k++) {
        const int c = ty + 32 * k;
        const float* fc = fb + (size_t)c * W * W + xi;
        float a = 0.f;
        #pragma unroll
        for (int j = 0; j < 7; j++) {
            int yj = min(ylo + j, W - 1);
            a += wy[j] * __ldg(fc + yj * W);
        }
        a *= wx;
        a += __shfl_xor_sync(0xffffffffu, a, 1);
        a += __shfl_xor_sync(0xffffffffu, a, 2);
        a += __shfl_xor_sync(0xffffffffu, a, 4);
        if (tx == 0)
            g_tmpl[((size_t)(level * BB + b) * CC + c) * NN + n] = a * inv;
    }
}

// ---------------------------------------------------------------------------
// Kernel 2: correlation + class-max + concat. 672 blocks x 256 thr,
// block = (level, b, 16-pixel tile); templates staged in smem (64KB ->
// 3 blocks/SM resident vs R4's 2.27). Warp: px8 = lane&7, cg = lane>>3;
// up = warp&3 (16 users/thread); pb = warp>>2. acc[j] = users (2j, 2j+1).
// Feat prefetched one channel ahead; template LDS via C++ (schedulable).
// ---------------------------------------------------------------------------
__global__ void __launch_bounds__(256) cor_kernel(
    const float* __restrict__ x0, const float* __restrict__ x1,
    const float* __restrict__ x2, const int* __restrict__ labp,
    float* __restrict__ out)
{
    extern __shared__ float sT[];             // 4 * CGPAD floats
    __shared__ int   slab[NN];
    __shared__ float pcmax[4][NCLS][16];

    const int bid = blockIdx.x;               // [0, 672)
    int level, b, tile;
    if (bid < 512)      { level = 0; b = bid >> 8;              tile = bid & 255; }
    else if (bid < 640) { level = 1; int q = bid - 512; b = q >> 6; tile = q & 63; }
    else                { level = 2; int q = bid - 640; b = q >> 4; tile = q & 15; }

    const int W  = 64 >> level;
    const int HW = W * W;
    const float* feat = (level == 0) ? x0 : (level == 1) ? x1 : x2;
    const size_t outOff = (level == 0) ? 0
                        : (level == 1) ? (size_t)(BB * 266 * 4096)
                        : (size_t)(BB * 266 * (4096 + 1024));

    // stage templates (16B pad between cgroups) + labels
    {
        const float4* src = (const float4*)(g_tmpl + (size_t)(level * BB + b) * CC * NN);
        float4* dst = (float4*)sT;
        #pragma unroll 4
        for (int i = threadIdx.x; i < CC * NN / 4; i += 256) {
            int cgi = i >> 10;                // 1024 float4 per cgroup
            dst[cgi * (CGPAD / 4) + (i & 1023)] = __ldg(src + i);
        }
        if (threadIdx.x < NN) {
            int lstr = lab_stride(labp);
            slab[threadIdx.x] = labp[(b * NN + threadIdx.x) * lstr];
        }
    }
    __syncthreads();

    const int lane = threadIdx.x & 31;
    const int warp = threadIdx.x >> 5;
    const int px8  = lane & 7;
    const int cg   = lane >> 3;               // channel group 0..3
    const int up   = warp & 3;                // user quarter 0..3
    const int pb   = warp >> 2;               // pixel octet 0..1
    const int p    = tile * 16 + pb * 8 + px8;

    const float* fp = feat + ((size_t)(b * CC + cg * 64)) * HW + p;
    float*       op = out + outOff + ((size_t)(b * 266 + cg * 64)) * HW + p;

    // this thread's 16 users: base sT + cg*CGPAD + up*16, stride 64 floats/ch
    const float* sptr = sT + cg * CGPAD + up * 16;

    unsigned long long acc[8];                // acc[j] = users (2j, 2j+1)
    #pragma unroll
    for (int i = 0; i < 8; i++) acc[i] = 0ULL;

    float fcur = __ldg(fp);
    #pragma unroll 8
    for (int c = 0; c < 64; c++) {
        const float fnext = __ldg(fp + (size_t)min(c + 1, 63) * HW);  // prefetch
        if (up == 0) op[(size_t)c * HW] = fcur;  // feat passthrough (warp-uniform)
        unsigned long long f2;
        {
            uint32_t fb_ = __float_as_uint(fcur);
            asm("mov.b64 %0, {%1, %1};" : "=l"(f2) : "r"(fb_));
        }
        const ulonglong2* tc = (const ulonglong2*)(sptr + c * 64);
        #pragma unroll
        for (int q = 0; q < 4; q++) {
            ulonglong2 t = tc[q];             // LDS.128: users 4q..4q+3
            asm("fma.rn.f32x2 %0, %1, %2, %0;" : "+l"(acc[2 * q])     : "l"(t.x), "l"(f2));
            asm("fma.rn.f32x2 %0, %1, %2, %0;" : "+l"(acc[2 * q + 1]) : "l"(t.y), "l"(f2));
        }
        fcur = fnext;
    }

    // sum the 4 channel groups (packed adds over lane bits 3,4)
    #pragma unroll
    for (int i = 0; i < 8; i++) {
        unsigned long long o = __shfl_xor_sync(0xffffffffu, acc[i], 8);
        asm("add.rn.f32x2 %0, %0, %1;" : "+l"(acc[i]) : "l"(o));
        o = __shfl_xor_sync(0xffffffffu, acc[i], 16);
        asm("add.rn.f32x2 %0, %0, %1;" : "+l"(acc[i]) : "l"(o));
    }

    // lanes cg==0 hold full 256-channel sums for this warp's 16 users
    if (cg == 0) {
        #pragma unroll
        for (int k = 0; k < NCLS; k++) {
            float m = -FLT_MAX;
            #pragma unroll
            for (int u = 0; u < 16; u++) {
                float v = (u & 1) ? __uint_as_float((uint32_t)(acc[u >> 1] >> 32))
                                  : __uint_as_float((uint32_t)(acc[u >> 1] & 0xffffffffu));
                if (slab[up * 16 + u] == k + 1) m = fmaxf(m, v);
            }
            pcmax[up][k][pb * 8 + px8] = m;
        }
    }
    __syncthreads();

    // combine 4 user quarters, apply any_cls -> 0, write class channels
    for (int t = threadIdx.x; t < NCLS * 16; t += 256) {
        const int k   = t >> 4;
        const int pix = t & 15;
        float v = fmaxf(fmaxf(pcmax[0][k][pix], pcmax[1][k][pix]),
                        fmaxf(pcmax[2][k][pix], pcmax[3][k][pix]));
        if (v == -FLT_MAX) v = 0.f;
        out[outOff + ((size_t)(b * 266 + 256 + k)) * HW + tile * 16 + pix] = v;
    }
}

// ---------------------------------------------------------------------------
extern "C" void kernel_launch(void* const* d_in, const int* in_sizes, int n_in,
                              void* d_out, int out_size)
{
    const float* x0      = (const float*)d_in[0];
    const float* x1      = (const float*)d_in[1];
    const float* x2      = (const float*)d_in[2];
    const float* centers = (const float*)d_in[3];
    const int*   idxp    = (const int*)d_in[4];
    const int*   labp    = (const int*)d_in[5];
    float* out = (float*)d_out;

    const int smem = 4 * CGPAD * (int)sizeof(float);
    cudaFuncSetAttribute(cor_kernel, cudaFuncAttributeMaxDynamicSharedMemorySize, smem);

    tmpl_kernel<<<3 * BB * NN, 256>>>(x0, x1, x2, centers, idxp, labp);
    cor_kernel<<<672, 256, smem>>>(x0, x1, x2, labp, out);
}